// round 2
// baseline (speedup 1.0000x reference)
#include <cuda_runtime.h>
#include <math.h>

#define NSEQ 3072
#define EMB 768
#define NHEAD 12
#define DHEAD 64
#define NLAYER 4
#define FFDIM 3072

// -------------------- scratch (device globals; no allocations allowed) -----
__device__ float g_out[NSEQ * EMB];
__device__ float g_q[NSEQ * EMB];
__device__ float g_k[NSEQ * EMB];
__device__ float g_v[NSEQ * EMB];
__device__ float g_att[NSEQ * EMB];
__device__ float g_tmp[NSEQ * EMB];
__device__ float g_xm[NSEQ * EMB];
__device__ float g_ff[NSEQ * FFDIM];

// -------------------- SGEMM: C[M,N] = A[M,K] @ B[N,K]^T (+ epilogue) -------
enum { MODE_NONE = 0, MODE_EMBED = 1, MODE_RES = 2, MODE_BRELU = 3, MODE_BRES = 4 };

template <int MODE>
__global__ __launch_bounds__(256, 1) void sgemm_kernel(
    const float* __restrict__ A, const float* __restrict__ B, float* __restrict__ C,
    int M, int N, int K, const float* __restrict__ bias, const float* __restrict__ extra)
{
    __shared__ float As[8][128];
    __shared__ float Bs[8][128];
    const int tid = threadIdx.x;
    const int bm = blockIdx.y * 128;
    const int bn = blockIdx.x * 128;
    const int lr = tid & 127;          // 0..127 row within tile
    const int lc = (tid >> 7) << 2;    // 0 or 4
    const float* Ap = A + (size_t)(bm + lr) * K + lc;
    const float* Bp = B + (size_t)(bn + lr) * K + lc;
    const int tx = tid & 15, ty = tid >> 4;

    float acc[8][8];
#pragma unroll
    for (int i = 0; i < 8; i++)
#pragma unroll
        for (int j = 0; j < 8; j++) acc[i][j] = 0.f;

    for (int k0 = 0; k0 < K; k0 += 8) {
        float4 a4 = *(const float4*)(Ap + k0);
        float4 b4 = *(const float4*)(Bp + k0);
        As[lc + 0][lr] = a4.x; As[lc + 1][lr] = a4.y;
        As[lc + 2][lr] = a4.z; As[lc + 3][lr] = a4.w;
        Bs[lc + 0][lr] = b4.x; Bs[lc + 1][lr] = b4.y;
        Bs[lc + 2][lr] = b4.z; Bs[lc + 3][lr] = b4.w;
        __syncthreads();
#pragma unroll
        for (int k = 0; k < 8; k++) {
            float ra[8], rb[8];
            *(float4*)(ra)     = *(const float4*)&As[k][ty * 8];
            *(float4*)(ra + 4) = *(const float4*)&As[k][ty * 8 + 4];
            *(float4*)(rb)     = *(const float4*)&Bs[k][tx * 8];
            *(float4*)(rb + 4) = *(const float4*)&Bs[k][tx * 8 + 4];
#pragma unroll
            for (int i = 0; i < 8; i++)
#pragma unroll
                for (int j = 0; j < 8; j++)
                    acc[i][j] = fmaf(ra[i], rb[j], acc[i][j]);
        }
        __syncthreads();
    }

#pragma unroll
    for (int i = 0; i < 8; i++) {
        const int r = bm + ty * 8 + i;
#pragma unroll
        for (int j = 0; j < 8; j++) {
            const int c = bn + tx * 8 + j;
            float v = acc[i][j];
            if (MODE == MODE_EMBED)      v = truncf(v + bias[c]) + extra[(size_t)r * N + c];
            else if (MODE == MODE_RES)   v = v + extra[(size_t)r * N + c];
            else if (MODE == MODE_BRELU) { v += bias[c]; v = v > 0.f ? v : 0.f; }
            else if (MODE == MODE_BRES)  v = v + bias[c] + extra[(size_t)r * N + c];
            C[(size_t)r * N + c] = v;
        }
    }
}

// QKV fused: one launch, blockIdx.z selects {Wq->q, Wk->k, Wv->v}. Same math
// as three MODE_NONE sgemm launches (bit-identical per-GEMM inner loop).
__global__ __launch_bounds__(256, 1) void qkv_kernel(
    const float* __restrict__ A,
    const float* __restrict__ Wq, const float* __restrict__ Wk, const float* __restrict__ Wv,
    float* __restrict__ Cq, float* __restrict__ Ck, float* __restrict__ Cv)
{
    __shared__ float As[8][128];
    __shared__ float Bs[8][128];
    const int tid = threadIdx.x;
    const int bm = blockIdx.y * 128;
    const int bn = blockIdx.x * 128;
    const float* B = (blockIdx.z == 0) ? Wq : (blockIdx.z == 1) ? Wk : Wv;
    float* C = (blockIdx.z == 0) ? Cq : (blockIdx.z == 1) ? Ck : Cv;
    const int lr = tid & 127;
    const int lc = (tid >> 7) << 2;
    const float* Ap = A + (size_t)(bm + lr) * EMB + lc;
    const float* Bp = B + (size_t)(bn + lr) * EMB + lc;
    const int tx = tid & 15, ty = tid >> 4;

    float acc[8][8];
#pragma unroll
    for (int i = 0; i < 8; i++)
#pragma unroll
        for (int j = 0; j < 8; j++) acc[i][j] = 0.f;

    for (int k0 = 0; k0 < EMB; k0 += 8) {
        float4 a4 = *(const float4*)(Ap + k0);
        float4 b4 = *(const float4*)(Bp + k0);
        As[lc + 0][lr] = a4.x; As[lc + 1][lr] = a4.y;
        As[lc + 2][lr] = a4.z; As[lc + 3][lr] = a4.w;
        Bs[lc + 0][lr] = b4.x; Bs[lc + 1][lr] = b4.y;
        Bs[lc + 2][lr] = b4.z; Bs[lc + 3][lr] = b4.w;
        __syncthreads();
#pragma unroll
        for (int k = 0; k < 8; k++) {
            float ra[8], rb[8];
            *(float4*)(ra)     = *(const float4*)&As[k][ty * 8];
            *(float4*)(ra + 4) = *(const float4*)&As[k][ty * 8 + 4];
            *(float4*)(rb)     = *(const float4*)&Bs[k][tx * 8];
            *(float4*)(rb + 4) = *(const float4*)&Bs[k][tx * 8 + 4];
#pragma unroll
            for (int i = 0; i < 8; i++)
#pragma unroll
                for (int j = 0; j < 8; j++)
                    acc[i][j] = fmaf(ra[i], rb[j], acc[i][j]);
        }
        __syncthreads();
    }

#pragma unroll
    for (int i = 0; i < 8; i++) {
        const int r = bm + ty * 8 + i;
#pragma unroll
        for (int j = 0; j < 8; j++) {
            const int c = bn + tx * 8 + j;
            C[(size_t)r * EMB + c] = acc[i][j];
        }
    }
}

// -------------------- flash attention (fp32, 64x64 tiles, d=64) ------------
__global__ __launch_bounds__(256, 1) void flash_kernel(
    const float* __restrict__ Q, const float* __restrict__ Kg,
    const float* __restrict__ Vg, float* __restrict__ O)
{
    __shared__ float sQ[64 * 64];
    __shared__ float sKV[64 * 64];  // K^T first, then V (normal) per iteration
    __shared__ float sS[64 * 64];
    const int h = blockIdx.y;
    const int q0 = blockIdx.x * 64;
    const int tid = threadIdx.x;
    const int tx = tid & 15, ty = tid >> 4;
    const int hoff = h * DHEAD;
    const float rscale = 0.03608439182435161f;  // 1/sqrt(768)

    // load Q tile, scale folded in
    for (int i = tid; i < 64 * 16; i += 256) {
        int r = i >> 4, c = (i & 15) << 2;
        float4 v = *(const float4*)(Q + (size_t)(q0 + r) * EMB + hoff + c);
        sQ[r * 64 + c + 0] = v.x * rscale;
        sQ[r * 64 + c + 1] = v.y * rscale;
        sQ[r * 64 + c + 2] = v.z * rscale;
        sQ[r * 64 + c + 3] = v.w * rscale;
    }

    float o[4][4];
#pragma unroll
    for (int i = 0; i < 4; i++)
#pragma unroll
        for (int j = 0; j < 4; j++) o[i][j] = 0.f;
    float mrow[4] = {-INFINITY, -INFINITY, -INFINITY, -INFINITY};
    float lrow[4] = {0.f, 0.f, 0.f, 0.f};

    for (int kb = 0; kb < NSEQ; kb += 64) {
        // K tile, stored transposed: sKV[k*64 + key]. Warp spans key index ->
        // conflict-free transpose store (banks = key % 32, all distinct).
        for (int i = tid; i < 64 * 16; i += 256) {
            int r = i & 63;            // key index
            int kq = (i >> 6) << 2;    // k base (0,4,...,60)
            float4 v = *(const float4*)(Kg + (size_t)(kb + r) * EMB + hoff + kq);
            sKV[(kq + 0) * 64 + r] = v.x;
            sKV[(kq + 1) * 64 + r] = v.y;
            sKV[(kq + 2) * 64 + r] = v.z;
            sKV[(kq + 3) * 64 + r] = v.w;
        }
        __syncthreads();

        // S = Qs @ K^T
        float s[4][4];
#pragma unroll
        for (int i = 0; i < 4; i++)
#pragma unroll
            for (int j = 0; j < 4; j++) s[i][j] = 0.f;
#pragma unroll
        for (int k0 = 0; k0 < 64; k0 += 4) {
            float a[4][4];
#pragma unroll
            for (int i = 0; i < 4; i++)
                *(float4*)a[i] = *(const float4*)&sQ[(ty * 4 + i) * 64 + k0];
#pragma unroll
            for (int kk = 0; kk < 4; kk++) {
                float4 b4 = *(const float4*)&sKV[(k0 + kk) * 64 + tx * 4];
                float b[4] = {b4.x, b4.y, b4.z, b4.w};
#pragma unroll
                for (int i = 0; i < 4; i++)
#pragma unroll
                    for (int j = 0; j < 4; j++)
                        s[i][j] = fmaf(a[i][kk], b[j], s[i][j]);
            }
        }

        // online softmax update (row groups of 16 tx-lanes)
#pragma unroll
        for (int i = 0; i < 4; i++) {
            float mx = fmaxf(fmaxf(s[i][0], s[i][1]), fmaxf(s[i][2], s[i][3]));
#pragma unroll
            for (int m = 8; m; m >>= 1) mx = fmaxf(mx, __shfl_xor_sync(0xffffffffu, mx, m));
            float mnew = fmaxf(mrow[i], mx);
            float corr = __expf(mrow[i] - mnew);
            float rs = 0.f;
#pragma unroll
            for (int j = 0; j < 4; j++) {
                float p = __expf(s[i][j] - mnew);
                s[i][j] = p;
                rs += p;
            }
#pragma unroll
            for (int m = 8; m; m >>= 1) rs += __shfl_xor_sync(0xffffffffu, rs, m);
            lrow[i] = lrow[i] * corr + rs;
            mrow[i] = mnew;
#pragma unroll
            for (int j = 0; j < 4; j++) o[i][j] *= corr;
            *(float4*)&sS[(ty * 4 + i) * 64 + tx * 4] =
                make_float4(s[i][0], s[i][1], s[i][2], s[i][3]);
        }
        __syncthreads();  // P written; everyone done with K tile

        // V tile, normal layout sKV[key*64 + c]
        for (int i = tid; i < 64 * 16; i += 256) {
            int r = i >> 4, c = (i & 15) << 2;
            float4 v = *(const float4*)(Vg + (size_t)(kb + r) * EMB + hoff + c);
            *(float4*)&sKV[r * 64 + c] = v;
        }
        __syncthreads();

        // O += P @ V
#pragma unroll
        for (int k0 = 0; k0 < 64; k0 += 4) {
            float p[4][4];
#pragma unroll
            for (int i = 0; i < 4; i++)
                *(float4*)p[i] = *(const float4*)&sS[(ty * 4 + i) * 64 + k0];
#pragma unroll
            for (int kk = 0; kk < 4; kk++) {
                float4 v4 = *(const float4*)&sKV[(k0 + kk) * 64 + tx * 4];
                float b[4] = {v4.x, v4.y, v4.z, v4.w};
#pragma unroll
                for (int i = 0; i < 4; i++)
#pragma unroll
                    for (int j = 0; j < 4; j++)
                        o[i][j] = fmaf(p[i][kk], b[j], o[i][j]);
            }
        }
        __syncthreads();  // before next iteration reuses sKV / sS
    }

#pragma unroll
    for (int i = 0; i < 4; i++) {
        float inv = 1.0f / lrow[i];
        float4 w = make_float4(o[i][0] * inv, o[i][1] * inv, o[i][2] * inv, o[i][3] * inv);
        *(float4*)(O + (size_t)(q0 + ty * 4 + i) * EMB + hoff + tx * 4) = w;
    }
}

// -------------------- layernorm over last dim (768), one block per row -----
__global__ __launch_bounds__(256, 1) void ln_kernel(
    const float* __restrict__ in, float* __restrict__ out,
    const float* __restrict__ g, const float* __restrict__ b)
{
    __shared__ float rs[8], rs2[8];
    __shared__ float s_mu, s_rstd;
    const int r = blockIdx.x;
    const int tid = threadIdx.x;
    const float* row = in + (size_t)r * EMB;
    float v0 = row[tid], v1 = row[tid + 256], v2 = row[tid + 512];
    float s = v0 + v1 + v2;
    float s2 = v0 * v0 + v1 * v1 + v2 * v2;
#pragma unroll
    for (int m = 16; m; m >>= 1) {
        s += __shfl_xor_sync(0xffffffffu, s, m);
        s2 += __shfl_xor_sync(0xffffffffu, s2, m);
    }
    if ((tid & 31) == 0) { rs[tid >> 5] = s; rs2[tid >> 5] = s2; }
    __syncthreads();
    if (tid == 0) {
        float S = 0.f, S2 = 0.f;
#pragma unroll
        for (int i = 0; i < 8; i++) { S += rs[i]; S2 += rs2[i]; }
        float mu = S * (1.0f / EMB);
        float var = S2 * (1.0f / EMB) - mu * mu;
        s_mu = mu;
        s_rstd = rsqrtf(var + 1e-5f);
    }
    __syncthreads();
    float mu = s_mu, rstd = s_rstd;
    float* orow = out + (size_t)r * EMB;
    orow[tid]       = (v0 - mu) * rstd * g[tid]       + b[tid];
    orow[tid + 256] = (v1 - mu) * rstd * g[tid + 256] + b[tid + 256];
    orow[tid + 512] = (v2 - mu) * rstd * g[tid + 512] + b[tid + 512];
}

// -------------------- mean over sequence -----------------------------------
__global__ void mean_kernel(const float* __restrict__ in, float* __restrict__ out)
{
    int e = blockIdx.x * 256 + threadIdx.x;
    float s = 0.f;
    for (int n = 0; n < NSEQ; n++) s += in[(size_t)n * EMB + e];
    out[e] = s * (1.0f / NSEQ);
}

// -------------------- launch ------------------------------------------------
extern "C" void kernel_launch(void* const* d_in, const int* in_sizes, int n_in,
                              void* d_out, int out_size)
{
    (void)in_sizes; (void)n_in; (void)out_size;
    const float* x      = (const float*)d_in[0];
    // d_in[1] = mask: mathematically unused in the reference
    const float* W_word = (const float*)d_in[2];
    const float* b_word = (const float*)d_in[3];
    const float* pos    = (const float*)d_in[4];
    const float* Wq     = (const float*)d_in[5];
    const float* Wk     = (const float*)d_in[6];
    const float* Wv     = (const float*)d_in[7];
    const float* Wo     = (const float*)d_in[8];
    const float* W1     = (const float*)d_in[9];
    const float* b1     = (const float*)d_in[10];
    const float* W2     = (const float*)d_in[11];
    const float* b2     = (const float*)d_in[12];
    const float* g1     = (const float*)d_in[13];
    const float* be1    = (const float*)d_in[14];
    const float* g2     = (const float*)d_in[15];
    const float* be2    = (const float*)d_in[16];
    float* out = (float*)d_out;

    float *p_out, *p_q, *p_k, *p_v, *p_att, *p_tmp, *p_xm, *p_ff;
    cudaGetSymbolAddress((void**)&p_out, g_out);
    cudaGetSymbolAddress((void**)&p_q,   g_q);
    cudaGetSymbolAddress((void**)&p_k,   g_k);
    cudaGetSymbolAddress((void**)&p_v,   g_v);
    cudaGetSymbolAddress((void**)&p_att, g_att);
    cudaGetSymbolAddress((void**)&p_tmp, g_tmp);
    cudaGetSymbolAddress((void**)&p_xm,  g_xm);
    cudaGetSymbolAddress((void**)&p_ff,  g_ff);

    dim3 blk(256);
    dim3 gEE(EMB / 128, NSEQ / 128);       // 6 x 24
    dim3 gQKV(EMB / 128, NSEQ / 128, 3);   // 6 x 24 x 3
    dim3 gFF(FFDIM / 128, NSEQ / 128);     // 24 x 24

    // embed: out = trunc(x @ Ww^T + b_word) + pos
    sgemm_kernel<MODE_EMBED><<<gEE, blk>>>(x, W_word, p_out, NSEQ, EMB, EMB, b_word, pos);

    for (int l = 0; l < NLAYER; l++) {
        const float* wq = Wq + (size_t)l * EMB * EMB;
        const float* wk = Wk + (size_t)l * EMB * EMB;
        const float* wv = Wv + (size_t)l * EMB * EMB;
        const float* wo = Wo + (size_t)l * EMB * EMB;
        const float* w1 = W1 + (size_t)l * FFDIM * EMB;
        const float* w2 = W2 + (size_t)l * EMB * FFDIM;

        qkv_kernel<<<gQKV, blk>>>(p_out, wq, wk, wv, p_q, p_k, p_v);

        flash_kernel<<<dim3(NSEQ / 64, NHEAD), blk>>>(p_q, p_k, p_v, p_att);

        // tmp = att @ Wo^T + out ; xm = LN(tmp)
        sgemm_kernel<MODE_RES><<<gEE, blk>>>(p_att, wo, p_tmp, NSEQ, EMB, EMB, nullptr, p_out);
        ln_kernel<<<NSEQ, 256>>>(p_tmp, p_xm, g1 + (size_t)l * EMB, be1 + (size_t)l * EMB);

        // ff = relu(xm @ W1^T + b1)
        sgemm_kernel<MODE_BRELU><<<gFF, blk>>>(p_xm, w1, p_ff, NSEQ, FFDIM, EMB,
                                               b1 + (size_t)l * FFDIM, nullptr);
        // tmp = ff @ W2^T + b2 + xm ; out = LN(tmp)
        sgemm_kernel<MODE_BRES><<<gEE, blk>>>(p_ff, w2, p_tmp, NSEQ, EMB, FFDIM,
                                              b2 + (size_t)l * EMB, p_xm);
        ln_kernel<<<NSEQ, 256>>>(p_tmp, p_out, g2 + (size_t)l * EMB, be2 + (size_t)l * EMB);
    }

    mean_kernel<<<3, 256>>>(p_out, out);
}

// round 9
// speedup vs baseline: 1.6254x; 1.6254x over previous
#include <cuda_runtime.h>
#include <cuda_bf16.h>
#include <math.h>
#include <stdint.h>

#define NSEQ 3072
#define EMB 768
#define NHEAD 12
#define DHEAD 64
#define NLAYER 4
#define FFDIM 3072

// -------------------- scratch (device globals; no allocations allowed) -----
__device__ float g_out[NSEQ * EMB];
__device__ float g_q[NSEQ * EMB];
__device__ float g_k[NSEQ * EMB];
__device__ float g_v[NSEQ * EMB];
__device__ float g_att[NSEQ * EMB];
__device__ float g_tmp[NSEQ * EMB];
__device__ float g_xm[NSEQ * EMB];
__device__ float g_ff[NSEQ * FFDIM];

// ==================== helpers ==============================================
__device__ __forceinline__ uint32_t smem_u32(const void* p) {
    uint32_t a;
    asm("{ .reg .u64 t; cvta.to.shared.u64 t, %1; cvt.u32.u64 %0, t; }" : "=r"(a) : "l"(p));
    return a;
}

#define LDMX4(R, addr) \
    asm volatile("ldmatrix.sync.aligned.m8n8.x4.shared.b16 {%0,%1,%2,%3}, [%4];" \
        : "=r"((R)[0]), "=r"((R)[1]), "=r"((R)[2]), "=r"((R)[3]) : "r"(addr))

#define MMA16816(D, Af, B0, B1) \
    asm volatile("mma.sync.aligned.m16n8k16.row.col.f32.bf16.bf16.f32 " \
        "{%0,%1,%2,%3}, {%4,%5,%6,%7}, {%8,%9}, {%0,%1,%2,%3};" \
        : "+f"((D)[0]), "+f"((D)[1]), "+f"((D)[2]), "+f"((D)[3]) \
        : "r"((Af)[0]), "r"((Af)[1]), "r"((Af)[2]), "r"((Af)[3]), "r"(B0), "r"(B1))

// smem tile stride: 40 halfs (80 B) -> ldmatrix rows start at banks
// {0,20,8,28,16,4,24,12}: conflict-free without swizzle.
#define TSTR 40

// ==================== bf16x3 HMMA GEMM core ================================
// C[M,N] = A[M,K] @ B[N,K]^T (+ epilogue). M,N multiples of 128, K of 32.
enum { MODE_NONE = 0, MODE_RES = 2, MODE_BRELU = 3, MODE_BRES = 4 };

struct GemmSmem {
    __nv_bfloat16 Ahi[128 * TSTR];
    __nv_bfloat16 Alo[128 * TSTR];
    __nv_bfloat16 Bhi[128 * TSTR];
    __nv_bfloat16 Blo[128 * TSTR];
};

__device__ __forceinline__ void cvt_store(
    __nv_bfloat16* hi, __nv_bfloat16* lo, int off, float4 a)
{
    __nv_bfloat162 h0 = __floats2bfloat162_rn(a.x, a.y);
    __nv_bfloat162 h1 = __floats2bfloat162_rn(a.z, a.w);
    float2 f0 = __bfloat1622float2(h0);
    float2 f1 = __bfloat1622float2(h1);
    __nv_bfloat162 l0 = __floats2bfloat162_rn(a.x - f0.x, a.y - f0.y);
    __nv_bfloat162 l1 = __floats2bfloat162_rn(a.z - f1.x, a.w - f1.y);
    *(uint2*)(hi + off) = make_uint2(*(uint32_t*)&h0, *(uint32_t*)&h1);
    *(uint2*)(lo + off) = make_uint2(*(uint32_t*)&l0, *(uint32_t*)&l1);
}

template <int MODE>
__device__ __forceinline__ void gemm_core(
    GemmSmem* sm,
    const float* __restrict__ A, const float* __restrict__ B, float* __restrict__ C,
    int N, int K, const float* __restrict__ bias, const float* __restrict__ extra)
{
    const int tid = threadIdx.x;
    const int lane = tid & 31;
    const int wid = tid >> 5;
    const int wm = (wid & 1) * 64;     // warp M offset in tile
    const int wn = (wid >> 1) * 32;    // warp N offset in tile
    const int bm = blockIdx.y * 128;
    const int bn = blockIdx.x * 128;
    const int sub = lane >> 3, r8 = lane & 7;

    const uint32_t aAhi = smem_u32(sm->Ahi);
    const uint32_t aAlo = smem_u32(sm->Alo);
    const uint32_t aBhi = smem_u32(sm->Bhi);
    const uint32_t aBlo = smem_u32(sm->Blo);

    float d[4][4][4];
#pragma unroll
    for (int i = 0; i < 4; i++)
#pragma unroll
        for (int j = 0; j < 4; j++)
#pragma unroll
            for (int k = 0; k < 4; k++) d[i][j][k] = 0.f;

    for (int k0 = 0; k0 < K; k0 += 32) {
        // ---- load 128x32 fp32 A and B, convert to hi/lo bf16 ----
#pragma unroll
        for (int i = 0; i < 4; i++) {
            int idx = i * 256 + tid;
            int row = idx >> 3;
            int c4 = (idx & 7) << 2;
            int soff = row * TSTR + c4;
            float4 a = *(const float4*)(A + (size_t)(bm + row) * K + k0 + c4);
            cvt_store(sm->Ahi, sm->Alo, soff, a);
            float4 b = *(const float4*)(B + (size_t)(bn + row) * K + k0 + c4);
            cvt_store(sm->Bhi, sm->Blo, soff, b);
        }
        __syncthreads();

#pragma unroll
        for (int kf = 0; kf < 2; kf++) {
            uint32_t ahi[4][4], alo[4][4], bhi[2][4], blo[2][4];
#pragma unroll
            for (int mi = 0; mi < 4; mi++) {
                int row = wm + mi * 16 + (sub & 1) * 8 + r8;
                int col = kf * 16 + (sub >> 1) * 8;
                uint32_t off = (uint32_t)(row * TSTR + col) * 2;
                LDMX4(ahi[mi], aAhi + off);
                LDMX4(alo[mi], aAlo + off);
            }
#pragma unroll
            for (int np = 0; np < 2; np++) {
                int row = wn + np * 16 + (sub >> 1) * 8 + r8;
                int col = kf * 16 + (sub & 1) * 8;
                uint32_t off = (uint32_t)(row * TSTR + col) * 2;
                LDMX4(bhi[np], aBhi + off);
                LDMX4(blo[np], aBlo + off);
            }
#pragma unroll
            for (int mi = 0; mi < 4; mi++)
#pragma unroll
                for (int ni = 0; ni < 4; ni++) {
                    const uint32_t h0 = bhi[ni >> 1][(ni & 1) * 2];
                    const uint32_t h1 = bhi[ni >> 1][(ni & 1) * 2 + 1];
                    const uint32_t l0 = blo[ni >> 1][(ni & 1) * 2];
                    const uint32_t l1 = blo[ni >> 1][(ni & 1) * 2 + 1];
                    MMA16816(d[mi][ni], ahi[mi], h0, h1);
                    MMA16816(d[mi][ni], ahi[mi], l0, l1);
                    MMA16816(d[mi][ni], alo[mi], h0, h1);
                }
        }
        __syncthreads();
    }

    // ---- epilogue ----
    const int er = lane >> 2, ec = (lane & 3) * 2;
#pragma unroll
    for (int mi = 0; mi < 4; mi++)
#pragma unroll
        for (int ni = 0; ni < 4; ni++) {
            const int col = bn + wn + ni * 8 + ec;
#pragma unroll
            for (int half = 0; half < 2; half++) {
                const int row = bm + wm + mi * 16 + er + half * 8;
                float2 v = make_float2(d[mi][ni][half * 2], d[mi][ni][half * 2 + 1]);
                if (MODE == MODE_RES) {
                    float2 e = *(const float2*)(extra + (size_t)row * N + col);
                    v.x += e.x; v.y += e.y;
                } else if (MODE == MODE_BRELU) {
                    v.x = fmaxf(v.x + bias[col], 0.f);
                    v.y = fmaxf(v.y + bias[col + 1], 0.f);
                } else if (MODE == MODE_BRES) {
                    float2 e = *(const float2*)(extra + (size_t)row * N + col);
                    v.x += bias[col] + e.x;
                    v.y += bias[col + 1] + e.y;
                }
                *(float2*)(C + (size_t)row * N + col) = v;
            }
        }
}

template <int MODE>
__global__ __launch_bounds__(256, 1) void mma_gemm(
    const float* __restrict__ A, const float* __restrict__ B, float* __restrict__ C,
    int N, int K, const float* __restrict__ bias, const float* __restrict__ extra)
{
    __shared__ GemmSmem sm;
    gemm_core<MODE>(&sm, A, B, C, N, K, bias, extra);
}

// QKV fused: blockIdx.z selects weight/output
__global__ __launch_bounds__(256, 1) void mma_qkv(
    const float* __restrict__ A,
    const float* __restrict__ Wq, const float* __restrict__ Wk, const float* __restrict__ Wv,
    float* __restrict__ Cq, float* __restrict__ Ck, float* __restrict__ Cv)
{
    __shared__ GemmSmem sm;
    const float* B = (blockIdx.z == 0) ? Wq : (blockIdx.z == 1) ? Wk : Wv;
    float* C = (blockIdx.z == 0) ? Cq : (blockIdx.z == 1) ? Ck : Cv;
    gemm_core<MODE_NONE>(&sm, A, B, C, EMB, EMB, nullptr, nullptr);
}

// -------------------- fp32 SGEMM (embed only: trunc is discontinuous) ------
__global__ __launch_bounds__(256, 1) void sgemm_embed(
    const float* __restrict__ A, const float* __restrict__ B, float* __restrict__ C,
    int M, int N, int K, const float* __restrict__ bias, const float* __restrict__ extra)
{
    __shared__ float As[8][128];
    __shared__ float Bs[8][128];
    const int tid = threadIdx.x;
    const int bm = blockIdx.y * 128;
    const int bn = blockIdx.x * 128;
    const int lr = tid & 127;
    const int lc = (tid >> 7) << 2;
    const float* Ap = A + (size_t)(bm + lr) * K + lc;
    const float* Bp = B + (size_t)(bn + lr) * K + lc;
    const int tx = tid & 15, ty = tid >> 4;

    float acc[8][8];
#pragma unroll
    for (int i = 0; i < 8; i++)
#pragma unroll
        for (int j = 0; j < 8; j++) acc[i][j] = 0.f;

    for (int k0 = 0; k0 < K; k0 += 8) {
        float4 a4 = *(const float4*)(Ap + k0);
        float4 b4 = *(const float4*)(Bp + k0);
        As[lc + 0][lr] = a4.x; As[lc + 1][lr] = a4.y;
        As[lc + 2][lr] = a4.z; As[lc + 3][lr] = a4.w;
        Bs[lc + 0][lr] = b4.x; Bs[lc + 1][lr] = b4.y;
        Bs[lc + 2][lr] = b4.z; Bs[lc + 3][lr] = b4.w;
        __syncthreads();
#pragma unroll
        for (int k = 0; k < 8; k++) {
            float ra[8], rb[8];
            *(float4*)(ra)     = *(const float4*)&As[k][ty * 8];
            *(float4*)(ra + 4) = *(const float4*)&As[k][ty * 8 + 4];
            *(float4*)(rb)     = *(const float4*)&Bs[k][tx * 8];
            *(float4*)(rb + 4) = *(const float4*)&Bs[k][tx * 8 + 4];
#pragma unroll
            for (int i = 0; i < 8; i++)
#pragma unroll
                for (int j = 0; j < 8; j++)
                    acc[i][j] = fmaf(ra[i], rb[j], acc[i][j]);
        }
        __syncthreads();
    }

#pragma unroll
    for (int i = 0; i < 8; i++) {
        const int r = bm + ty * 8 + i;
#pragma unroll
        for (int j = 0; j < 8; j++) {
            const int c = bn + tx * 8 + j;
            C[(size_t)r * N + c] = truncf(acc[i][j] + bias[c]) + extra[(size_t)r * N + c];
        }
    }
}

// -------------------- flash attention (fp32, 64x64 tiles, d=64) ------------
__global__ __launch_bounds__(256, 1) void flash_kernel(
    const float* __restrict__ Q, const float* __restrict__ Kg,
    const float* __restrict__ Vg, float* __restrict__ O)
{
    __shared__ float sQ[64 * 64];
    __shared__ float sKV[64 * 64];
    __shared__ float sS[64 * 64];
    const int h = blockIdx.y;
    const int q0 = blockIdx.x * 64;
    const int tid = threadIdx.x;
    const int tx = tid & 15, ty = tid >> 4;
    const int hoff = h * DHEAD;
    const float rscale = 0.03608439182435161f;  // 1/sqrt(768)

    for (int i = tid; i < 64 * 16; i += 256) {
        int r = i >> 4, c = (i & 15) << 2;
        float4 v = *(const float4*)(Q + (size_t)(q0 + r) * EMB + hoff + c);
        sQ[r * 64 + c + 0] = v.x * rscale;
        sQ[r * 64 + c + 1] = v.y * rscale;
        sQ[r * 64 + c + 2] = v.z * rscale;
        sQ[r * 64 + c + 3] = v.w * rscale;
    }

    float o[4][4];
#pragma unroll
    for (int i = 0; i < 4; i++)
#pragma unroll
        for (int j = 0; j < 4; j++) o[i][j] = 0.f;
    float mrow[4] = {-INFINITY, -INFINITY, -INFINITY, -INFINITY};
    float lrow[4] = {0.f, 0.f, 0.f, 0.f};

    for (int kb = 0; kb < NSEQ; kb += 64) {
        for (int i = tid; i < 64 * 16; i += 256) {
            int r = i & 63;
            int kq = (i >> 6) << 2;
            float4 v = *(const float4*)(Kg + (size_t)(kb + r) * EMB + hoff + kq);
            sKV[(kq + 0) * 64 + r] = v.x;
            sKV[(kq + 1) * 64 + r] = v.y;
            sKV[(kq + 2) * 64 + r] = v.z;
            sKV[(kq + 3) * 64 + r] = v.w;
        }
        __syncthreads();

        float s[4][4];
#pragma unroll
        for (int i = 0; i < 4; i++)
#pragma unroll
            for (int j = 0; j < 4; j++) s[i][j] = 0.f;
#pragma unroll
        for (int k0 = 0; k0 < 64; k0 += 4) {
            float a[4][4];
#pragma unroll
            for (int i = 0; i < 4; i++)
                *(float4*)a[i] = *(const float4*)&sQ[(ty * 4 + i) * 64 + k0];
#pragma unroll
            for (int kk = 0; kk < 4; kk++) {
                float4 b4 = *(const float4*)&sKV[(k0 + kk) * 64 + tx * 4];
                float b[4] = {b4.x, b4.y, b4.z, b4.w};
#pragma unroll
                for (int i = 0; i < 4; i++)
#pragma unroll
                    for (int j = 0; j < 4; j++)
                        s[i][j] = fmaf(a[i][kk], b[j], s[i][j]);
            }
        }

#pragma unroll
        for (int i = 0; i < 4; i++) {
            float mx = fmaxf(fmaxf(s[i][0], s[i][1]), fmaxf(s[i][2], s[i][3]));
#pragma unroll
            for (int m = 8; m; m >>= 1) mx = fmaxf(mx, __shfl_xor_sync(0xffffffffu, mx, m));
            float mnew = fmaxf(mrow[i], mx);
            float corr = __expf(mrow[i] - mnew);
            float rs = 0.f;
#pragma unroll
            for (int j = 0; j < 4; j++) {
                float p = __expf(s[i][j] - mnew);
                s[i][j] = p;
                rs += p;
            }
#pragma unroll
            for (int m = 8; m; m >>= 1) rs += __shfl_xor_sync(0xffffffffu, rs, m);
            lrow[i] = lrow[i] * corr + rs;
            mrow[i] = mnew;
#pragma unroll
            for (int j = 0; j < 4; j++) o[i][j] *= corr;
            *(float4*)&sS[(ty * 4 + i) * 64 + tx * 4] =
                make_float4(s[i][0], s[i][1], s[i][2], s[i][3]);
        }
        __syncthreads();

        for (int i = tid; i < 64 * 16; i += 256) {
            int r = i >> 4, c = (i & 15) << 2;
            float4 v = *(const float4*)(Vg + (size_t)(kb + r) * EMB + hoff + c);
            *(float4*)&sKV[r * 64 + c] = v;
        }
        __syncthreads();

#pragma unroll
        for (int k0 = 0; k0 < 64; k0 += 4) {
            float p[4][4];
#pragma unroll
            for (int i = 0; i < 4; i++)
                *(float4*)p[i] = *(const float4*)&sS[(ty * 4 + i) * 64 + k0];
#pragma unroll
            for (int kk = 0; kk < 4; kk++) {
                float4 v4 = *(const float4*)&sKV[(k0 + kk) * 64 + tx * 4];
                float b[4] = {v4.x, v4.y, v4.z, v4.w};
#pragma unroll
                for (int i = 0; i < 4; i++)
#pragma unroll
                    for (int j = 0; j < 4; j++)
                        o[i][j] = fmaf(p[i][kk], b[j], o[i][j]);
            }
        }
        __syncthreads();
    }

#pragma unroll
    for (int i = 0; i < 4; i++) {
        float inv = 1.0f / lrow[i];
        float4 w = make_float4(o[i][0] * inv, o[i][1] * inv, o[i][2] * inv, o[i][3] * inv);
        *(float4*)(O + (size_t)(q0 + ty * 4 + i) * EMB + hoff + tx * 4) = w;
    }
}

// -------------------- layernorm over last dim (768) ------------------------
__global__ __launch_bounds__(256, 1) void ln_kernel(
    const float* __restrict__ in, float* __restrict__ out,
    const float* __restrict__ g, const float* __restrict__ b)
{
    __shared__ float rs[8], rs2[8];
    __shared__ float s_mu, s_rstd;
    const int r = blockIdx.x;
    const int tid = threadIdx.x;
    const float* row = in + (size_t)r * EMB;
    float v0 = row[tid], v1 = row[tid + 256], v2 = row[tid + 512];
    float s = v0 + v1 + v2;
    float s2 = v0 * v0 + v1 * v1 + v2 * v2;
#pragma unroll
    for (int m = 16; m; m >>= 1) {
        s += __shfl_xor_sync(0xffffffffu, s, m);
        s2 += __shfl_xor_sync(0xffffffffu, s2, m);
    }
    if ((tid & 31) == 0) { rs[tid >> 5] = s; rs2[tid >> 5] = s2; }
    __syncthreads();
    if (tid == 0) {
        float S = 0.f, S2 = 0.f;
#pragma unroll
        for (int i = 0; i < 8; i++) { S += rs[i]; S2 += rs2[i]; }
        float mu = S * (1.0f / EMB);
        float var = S2 * (1.0f / EMB) - mu * mu;
        s_mu = mu;
        s_rstd = rsqrtf(var + 1e-5f);
    }
    __syncthreads();
    float mu = s_mu, rstd = s_rstd;
    float* orow = out + (size_t)r * EMB;
    orow[tid]       = (v0 - mu) * rstd * g[tid]       + b[tid];
    orow[tid + 256] = (v1 - mu) * rstd * g[tid + 256] + b[tid + 256];
    orow[tid + 512] = (v2 - mu) * rstd * g[tid + 512] + b[tid + 512];
}

// -------------------- mean over sequence -----------------------------------
__global__ void mean_kernel(const float* __restrict__ in, float* __restrict__ out)
{
    int e = blockIdx.x * 256 + threadIdx.x;
    float s = 0.f;
    for (int n = 0; n < NSEQ; n++) s += in[(size_t)n * EMB + e];
    out[e] = s * (1.0f / NSEQ);
}

// -------------------- launch ------------------------------------------------
extern "C" void kernel_launch(void* const* d_in, const int* in_sizes, int n_in,
                              void* d_out, int out_size)
{
    (void)in_sizes; (void)n_in; (void)out_size;
    const float* x      = (const float*)d_in[0];
    const float* W_word = (const float*)d_in[2];
    const float* b_word = (const float*)d_in[3];
    const float* pos    = (const float*)d_in[4];
    const float* Wq     = (const float*)d_in[5];
    const float* Wk     = (const float*)d_in[6];
    const float* Wv     = (const float*)d_in[7];
    const float* Wo     = (const float*)d_in[8];
    const float* W1     = (const float*)d_in[9];
    const float* b1     = (const float*)d_in[10];
    const float* W2     = (const float*)d_in[11];
    const float* b2     = (const float*)d_in[12];
    const float* g1     = (const float*)d_in[13];
    const float* be1    = (const float*)d_in[14];
    const float* g2     = (const float*)d_in[15];
    const float* be2    = (const float*)d_in[16];
    float* out = (float*)d_out;

    float *p_out, *p_q, *p_k, *p_v, *p_att, *p_tmp, *p_xm, *p_ff;
    cudaGetSymbolAddress((void**)&p_out, g_out);
    cudaGetSymbolAddress((void**)&p_q,   g_q);
    cudaGetSymbolAddress((void**)&p_k,   g_k);
    cudaGetSymbolAddress((void**)&p_v,   g_v);
    cudaGetSymbolAddress((void**)&p_att, g_att);
    cudaGetSymbolAddress((void**)&p_tmp, g_tmp);
    cudaGetSymbolAddress((void**)&p_xm,  g_xm);
    cudaGetSymbolAddress((void**)&p_ff,  g_ff);

    dim3 blk(256);
    dim3 gEE(EMB / 128, NSEQ / 128);       // 6 x 24
    dim3 gQKV(EMB / 128, NSEQ / 128, 3);   // 6 x 24 x 3
    dim3 gFF(FFDIM / 128, NSEQ / 128);     // 24 x 24

    // embed: out = trunc(x @ Ww^T + b_word) + pos   (fp32: trunc discontinuity)
    sgemm_embed<<<gEE, blk>>>(x, W_word, p_out, NSEQ, EMB, EMB, b_word, pos);

    for (int l = 0; l < NLAYER; l++) {
        const float* wq = Wq + (size_t)l * EMB * EMB;
        const float* wk = Wk + (size_t)l * EMB * EMB;
        const float* wv = Wv + (size_t)l * EMB * EMB;
        const float* wo = Wo + (size_t)l * EMB * EMB;
        const float* w1 = W1 + (size_t)l * FFDIM * EMB;
        const float* w2 = W2 + (size_t)l * EMB * FFDIM;

        mma_qkv<<<gQKV, blk>>>(p_out, wq, wk, wv, p_q, p_k, p_v);

        flash_kernel<<<dim3(NSEQ / 64, NHEAD), blk>>>(p_q, p_k, p_v, p_att);

        mma_gemm<MODE_RES><<<gEE, blk>>>(p_att, wo, p_tmp, EMB, EMB, nullptr, p_out);
        ln_kernel<<<NSEQ, 256>>>(p_tmp, p_xm, g1 + (size_t)l * EMB, be1 + (size_t)l * EMB);

        mma_gemm<MODE_BRELU><<<gFF, blk>>>(p_xm, w1, p_ff, FFDIM, EMB,
                                           b1 + (size_t)l * FFDIM, nullptr);
        mma_gemm<MODE_BRES><<<gEE, blk>>>(p_ff, w2, p_tmp, EMB, FFDIM,
                                          b2 + (size_t)l * EMB, p_xm);
        ln_kernel<<<NSEQ, 256>>>(p_tmp, p_out, g2 + (size_t)l * EMB, be2 + (size_t)l * EMB);
    }

    mean_kernel<<<3, 256>>>(p_out, out);
}

// round 12
// speedup vs baseline: 3.7513x; 2.3080x over previous
#include <cuda_runtime.h>
#include <cuda_bf16.h>
#include <math.h>
#include <stdint.h>

#define NSEQ 3072
#define EMB 768
#define NHEAD 12
#define DHEAD 64
#define NLAYER 4
#define FFDIM 3072

// -------------------- scratch (device globals; no allocations allowed) -----
__device__ float g_out[NSEQ * EMB];
__device__ float g_q[NSEQ * EMB];
__device__ float g_k[NSEQ * EMB];
__device__ float g_v[NSEQ * EMB];
__device__ float g_att[NSEQ * EMB];
__device__ float g_tmp[NSEQ * EMB];
__device__ float g_xm[NSEQ * EMB];
__device__ float g_ff[NSEQ * FFDIM];

// ==================== helpers ==============================================
__device__ __forceinline__ uint32_t smem_u32(const void* p) {
    uint32_t a;
    asm("{ .reg .u64 t; cvta.to.shared.u64 t, %1; cvt.u32.u64 %0, t; }" : "=r"(a) : "l"(p));
    return a;
}

#define LDMX4(R, addr) \
    asm volatile("ldmatrix.sync.aligned.m8n8.x4.shared.b16 {%0,%1,%2,%3}, [%4];" \
        : "=r"((R)[0]), "=r"((R)[1]), "=r"((R)[2]), "=r"((R)[3]) : "r"(addr))

#define LDMX4T(R, addr) \
    asm volatile("ldmatrix.sync.aligned.m8n8.x4.trans.shared.b16 {%0,%1,%2,%3}, [%4];" \
        : "=r"((R)[0]), "=r"((R)[1]), "=r"((R)[2]), "=r"((R)[3]) : "r"(addr))

#define MMA16816(D, Af, B0, B1) \
    asm volatile("mma.sync.aligned.m16n8k16.row.col.f32.bf16.bf16.f32 " \
        "{%0,%1,%2,%3}, {%4,%5,%6,%7}, {%8,%9}, {%0,%1,%2,%3};" \
        : "+f"((D)[0]), "+f"((D)[1]), "+f"((D)[2]), "+f"((D)[3]) \
        : "r"((Af)[0]), "r"((Af)[1]), "r"((Af)[2]), "r"((Af)[3]), "r"(B0), "r"(B1))

// GEMM smem tile stride: 40 halfs (80 B) -> conflict-free ldmatrix, no swizzle.
#define TSTR 40

// ==================== bf16x3 HMMA GEMM (double-buffered) ===================
// C[M,N] = A[M,K] @ B[N,K]^T (+ epilogue). M,N multiples of 128, K of 32.
enum { MODE_NONE = 0, MODE_RES = 2, MODE_BRELU = 3, MODE_BRES = 4 };

struct GemmSmem {
    __nv_bfloat16 Ahi[128 * TSTR];
    __nv_bfloat16 Alo[128 * TSTR];
    __nv_bfloat16 Bhi[128 * TSTR];
    __nv_bfloat16 Blo[128 * TSTR];
};
#define GEMM_DSMEM (2 * (int)sizeof(GemmSmem))   // 81920 B

__device__ __forceinline__ void cvt_store(
    __nv_bfloat16* hi, __nv_bfloat16* lo, int off, float4 a)
{
    __nv_bfloat162 h0 = __floats2bfloat162_rn(a.x, a.y);
    __nv_bfloat162 h1 = __floats2bfloat162_rn(a.z, a.w);
    float2 f0 = __bfloat1622float2(h0);
    float2 f1 = __bfloat1622float2(h1);
    __nv_bfloat162 l0 = __floats2bfloat162_rn(a.x - f0.x, a.y - f0.y);
    __nv_bfloat162 l1 = __floats2bfloat162_rn(a.z - f1.x, a.w - f1.y);
    *(uint2*)(hi + off) = make_uint2(*(uint32_t*)&h0, *(uint32_t*)&h1);
    *(uint2*)(lo + off) = make_uint2(*(uint32_t*)&l0, *(uint32_t*)&l1);
}

__device__ __forceinline__ void g_fetch(
    float4* pa, float4* pb, const float* A, const float* B,
    int bm, int bn, int K, int k0, int tid)
{
#pragma unroll
    for (int i = 0; i < 4; i++) {
        int idx = i * 256 + tid;
        int row = idx >> 3;
        int c4 = (idx & 7) << 2;
        pa[i] = *(const float4*)(A + (size_t)(bm + row) * K + k0 + c4);
        pb[i] = *(const float4*)(B + (size_t)(bn + row) * K + k0 + c4);
    }
}

__device__ __forceinline__ void g_commit(
    GemmSmem* st, const float4* pa, const float4* pb, int tid)
{
#pragma unroll
    for (int i = 0; i < 4; i++) {
        int idx = i * 256 + tid;
        int row = idx >> 3;
        int c4 = (idx & 7) << 2;
        int soff = row * TSTR + c4;
        cvt_store(st->Ahi, st->Alo, soff, pa[i]);
        cvt_store(st->Bhi, st->Blo, soff, pb[i]);
    }
}

template <int MODE>
__device__ __forceinline__ void gemm_core(
    GemmSmem* stages,
    const float* __restrict__ A, const float* __restrict__ B, float* __restrict__ C,
    int N, int K, const float* __restrict__ bias, const float* __restrict__ extra)
{
    const int tid = threadIdx.x;
    const int lane = tid & 31;
    const int wid = tid >> 5;
    const int wm = (wid & 1) * 64;
    const int wn = (wid >> 1) * 32;
    const int bm = blockIdx.y * 128;
    const int bn = blockIdx.x * 128;
    const int sub = lane >> 3, r8 = lane & 7;

    float d[4][4][4];
#pragma unroll
    for (int i = 0; i < 4; i++)
#pragma unroll
        for (int j = 0; j < 4; j++)
#pragma unroll
            for (int k = 0; k < 4; k++) d[i][j][k] = 0.f;

    const int nch = K >> 5;
    {
        float4 pa[4], pb[4];
        g_fetch(pa, pb, A, B, bm, bn, K, 0, tid);
        g_commit(&stages[0], pa, pb, tid);
    }
    __syncthreads();

    for (int c = 0; c < nch; c++) {
        float4 pa[4], pb[4];
        const bool more = (c + 1 < nch);
        if (more) g_fetch(pa, pb, A, B, bm, bn, K, (c + 1) << 5, tid);

        GemmSmem* st = &stages[c & 1];
        const uint32_t aAhi = smem_u32(st->Ahi);
        const uint32_t aAlo = smem_u32(st->Alo);
        const uint32_t aBhi = smem_u32(st->Bhi);
        const uint32_t aBlo = smem_u32(st->Blo);

#pragma unroll
        for (int kf = 0; kf < 2; kf++) {
            uint32_t ahi[4][4], alo[4][4], bhi[2][4], blo[2][4];
#pragma unroll
            for (int mi = 0; mi < 4; mi++) {
                int row = wm + mi * 16 + (sub & 1) * 8 + r8;
                int col = kf * 16 + (sub >> 1) * 8;
                uint32_t off = (uint32_t)(row * TSTR + col) * 2;
                LDMX4(ahi[mi], aAhi + off);
                LDMX4(alo[mi], aAlo + off);
            }
#pragma unroll
            for (int np = 0; np < 2; np++) {
                int row = wn + np * 16 + (sub >> 1) * 8 + r8;
                int col = kf * 16 + (sub & 1) * 8;
                uint32_t off = (uint32_t)(row * TSTR + col) * 2;
                LDMX4(bhi[np], aBhi + off);
                LDMX4(blo[np], aBlo + off);
            }
#pragma unroll
            for (int mi = 0; mi < 4; mi++)
#pragma unroll
                for (int ni = 0; ni < 4; ni++) {
                    const uint32_t h0 = bhi[ni >> 1][(ni & 1) * 2];
                    const uint32_t h1 = bhi[ni >> 1][(ni & 1) * 2 + 1];
                    const uint32_t l0 = blo[ni >> 1][(ni & 1) * 2];
                    const uint32_t l1 = blo[ni >> 1][(ni & 1) * 2 + 1];
                    MMA16816(d[mi][ni], ahi[mi], h0, h1);
                    MMA16816(d[mi][ni], ahi[mi], l0, l1);
                    MMA16816(d[mi][ni], alo[mi], h0, h1);
                }
        }
        if (more) g_commit(&stages[(c + 1) & 1], pa, pb, tid);
        __syncthreads();
    }

    // ---- epilogue ----
    const int er = lane >> 2, ec = (lane & 3) * 2;
#pragma unroll
    for (int mi = 0; mi < 4; mi++)
#pragma unroll
        for (int ni = 0; ni < 4; ni++) {
            const int col = bn + wn + ni * 8 + ec;
#pragma unroll
            for (int half = 0; half < 2; half++) {
                const int row = bm + wm + mi * 16 + er + half * 8;
                float2 v = make_float2(d[mi][ni][half * 2], d[mi][ni][half * 2 + 1]);
                if (MODE == MODE_RES) {
                    float2 e = *(const float2*)(extra + (size_t)row * N + col);
                    v.x += e.x; v.y += e.y;
                } else if (MODE == MODE_BRELU) {
                    v.x = fmaxf(v.x + bias[col], 0.f);
                    v.y = fmaxf(v.y + bias[col + 1], 0.f);
                } else if (MODE == MODE_BRES) {
                    float2 e = *(const float2*)(extra + (size_t)row * N + col);
                    v.x += bias[col] + e.x;
                    v.y += bias[col + 1] + e.y;
                }
                *(float2*)(C + (size_t)row * N + col) = v;
            }
        }
}

template <int MODE>
__global__ __launch_bounds__(256, 1) void mma_gemm(
    const float* __restrict__ A, const float* __restrict__ B, float* __restrict__ C,
    int N, int K, const float* __restrict__ bias, const float* __restrict__ extra)
{
    extern __shared__ char smraw[];
    gemm_core<MODE>((GemmSmem*)smraw, A, B, C, N, K, bias, extra);
}

__global__ __launch_bounds__(256, 1) void mma_qkv(
    const float* __restrict__ A,
    const float* __restrict__ Wq, const float* __restrict__ Wk, const float* __restrict__ Wv,
    float* __restrict__ Cq, float* __restrict__ Ck, float* __restrict__ Cv)
{
    extern __shared__ char smraw[];
    const float* B = (blockIdx.z == 0) ? Wq : (blockIdx.z == 1) ? Wk : Wv;
    float* C = (blockIdx.z == 0) ? Cq : (blockIdx.z == 1) ? Ck : Cv;
    gemm_core<MODE_NONE>((GemmSmem*)smraw, A, B, C, EMB, EMB, nullptr, nullptr);
}

// ==================== HMMA flash attention =================================
// 128 q-rows per CTA, 128-key tiles, d=64. 8 warps x 16 rows.
// QK^T: bf16 hi/lo 3-pass. P*V: plain bf16.
#define FTSTR 72   // 144B rows: ldmatrix row octets hit banks 4r%32 -> conflict-free

struct FlashSmem {
    __nv_bfloat16 Khi[128 * FTSTR];
    __nv_bfloat16 Klo[128 * FTSTR];
    __nv_bfloat16 Vt[128 * FTSTR];
};
#define FLASH_DSMEM ((int)sizeof(FlashSmem))   // 55296 B

__global__ __launch_bounds__(256, 1) void flash_hmma(
    const float* __restrict__ Q, const float* __restrict__ Kg,
    const float* __restrict__ Vg, float* __restrict__ O)
{
    extern __shared__ char smraw[];
    FlashSmem* sm = (FlashSmem*)smraw;
    const int tid = threadIdx.x;
    const int lane = tid & 31;
    const int wid = tid >> 5;
    const int sub = lane >> 3, r8 = lane & 7;
    const int er = lane >> 2, ec = (lane & 3) * 2;
    const int wm = wid * 16;
    const int q0 = blockIdx.x * 128;
    const int hoff = blockIdx.y * DHEAD;
    const float rscale = 0.03608439182435161f;  // 1/sqrt(768)

    const uint32_t aKhi = smem_u32(sm->Khi);
    const uint32_t aKlo = smem_u32(sm->Klo);
    const uint32_t aVt  = smem_u32(sm->Vt);

    // ---- load Q (scaled) into Khi/Klo staging, extract A-frags to regs ----
#pragma unroll
    for (int i = 0; i < 8; i++) {
        int idx = i * 256 + tid;
        int row = idx >> 4;
        int c4 = (idx & 15) << 2;
        float4 v = *(const float4*)(Q + (size_t)(q0 + row) * EMB + hoff + c4);
        v.x *= rscale; v.y *= rscale; v.z *= rscale; v.w *= rscale;
        cvt_store(sm->Khi, sm->Klo, row * FTSTR + c4, v);
    }
    __syncthreads();

    uint32_t qhi[4][4], qlo[4][4];
#pragma unroll
    for (int kf = 0; kf < 4; kf++) {
        uint32_t off = (uint32_t)((wm + (sub & 1) * 8 + r8) * FTSTR
                                  + kf * 16 + (sub >> 1) * 8) * 2;
        LDMX4(qhi[kf], aKhi + off);
        LDMX4(qlo[kf], aKlo + off);
    }
    __syncthreads();   // all warps done reading Q before K overwrites staging

    float o[8][4];
#pragma unroll
    for (int i = 0; i < 8; i++)
#pragma unroll
        for (int j = 0; j < 4; j++) o[i][j] = 0.f;
    float m0 = -INFINITY, m1 = -INFINITY, l0 = 0.f, l1 = 0.f;

    for (int kb = 0; kb < NSEQ; kb += 128) {
        // ---- load K (hi/lo) and V (plain bf16) tiles ----
#pragma unroll
        for (int i = 0; i < 8; i++) {
            int idx = i * 256 + tid;
            int row = idx >> 4;
            int c4 = (idx & 15) << 2;
            float4 kv = *(const float4*)(Kg + (size_t)(kb + row) * EMB + hoff + c4);
            cvt_store(sm->Khi, sm->Klo, row * FTSTR + c4, kv);
            float4 vv = *(const float4*)(Vg + (size_t)(kb + row) * EMB + hoff + c4);
            __nv_bfloat162 v0 = __floats2bfloat162_rn(vv.x, vv.y);
            __nv_bfloat162 v1 = __floats2bfloat162_rn(vv.z, vv.w);
            *(uint2*)(sm->Vt + row * FTSTR + c4) =
                make_uint2(*(uint32_t*)&v0, *(uint32_t*)&v1);
        }
        __syncthreads();

        // ---- S = Q*K^T (3-pass hi/lo), warp computes 16 rows x 128 keys ----
        float s[16][4];
#pragma unroll
        for (int ni = 0; ni < 16; ni++)
#pragma unroll
            for (int j = 0; j < 4; j++) s[ni][j] = 0.f;

#pragma unroll
        for (int kf = 0; kf < 4; kf++) {
#pragma unroll
            for (int np = 0; np < 8; np++) {
                uint32_t bh[4], bl[4];
                uint32_t off = (uint32_t)((np * 16 + (sub >> 1) * 8 + r8) * FTSTR
                                          + kf * 16 + (sub & 1) * 8) * 2;
                LDMX4(bh, aKhi + off);
                LDMX4(bl, aKlo + off);
                MMA16816(s[2 * np],     qhi[kf], bh[0], bh[1]);
                MMA16816(s[2 * np],     qhi[kf], bl[0], bl[1]);
                MMA16816(s[2 * np],     qlo[kf], bh[0], bh[1]);
                MMA16816(s[2 * np + 1], qhi[kf], bh[2], bh[3]);
                MMA16816(s[2 * np + 1], qhi[kf], bl[2], bl[3]);
                MMA16816(s[2 * np + 1], qlo[kf], bh[2], bh[3]);
            }
        }

        // ---- online softmax (rows er and er+8; 4-lane row groups) ----
        float mx0 = -INFINITY, mx1 = -INFINITY;
#pragma unroll
        for (int ni = 0; ni < 16; ni++) {
            mx0 = fmaxf(mx0, fmaxf(s[ni][0], s[ni][1]));
            mx1 = fmaxf(mx1, fmaxf(s[ni][2], s[ni][3]));
        }
#pragma unroll
        for (int msk = 1; msk < 4; msk <<= 1) {
            mx0 = fmaxf(mx0, __shfl_xor_sync(0xffffffffu, mx0, msk));
            mx1 = fmaxf(mx1, __shfl_xor_sync(0xffffffffu, mx1, msk));
        }
        float mn0 = fmaxf(m0, mx0), mn1 = fmaxf(m1, mx1);
        float c0 = __expf(m0 - mn0), c1 = __expf(m1 - mn1);
        float rs0 = 0.f, rs1 = 0.f;
#pragma unroll
        for (int ni = 0; ni < 16; ni++) {
            s[ni][0] = __expf(s[ni][0] - mn0); rs0 += s[ni][0];
            s[ni][1] = __expf(s[ni][1] - mn0); rs0 += s[ni][1];
            s[ni][2] = __expf(s[ni][2] - mn1); rs1 += s[ni][2];
            s[ni][3] = __expf(s[ni][3] - mn1); rs1 += s[ni][3];
        }
#pragma unroll
        for (int msk = 1; msk < 4; msk <<= 1) {
            rs0 += __shfl_xor_sync(0xffffffffu, rs0, msk);
            rs1 += __shfl_xor_sync(0xffffffffu, rs1, msk);
        }
        l0 = l0 * c0 + rs0;
        l1 = l1 * c1 + rs1;
        m0 = mn0; m1 = mn1;
#pragma unroll
        for (int nd = 0; nd < 8; nd++) {
            o[nd][0] *= c0; o[nd][1] *= c0;
            o[nd][2] *= c1; o[nd][3] *= c1;
        }

        // ---- O += P*V (P packed from accum regs into A-frags; bf16) ----
#pragma unroll
        for (int kq = 0; kq < 8; kq++) {
            uint32_t pa[4];
            __nv_bfloat162 t;
            t = __floats2bfloat162_rn(s[2 * kq][0],     s[2 * kq][1]);     pa[0] = *(uint32_t*)&t;
            t = __floats2bfloat162_rn(s[2 * kq][2],     s[2 * kq][3]);     pa[1] = *(uint32_t*)&t;
            t = __floats2bfloat162_rn(s[2 * kq + 1][0], s[2 * kq + 1][1]); pa[2] = *(uint32_t*)&t;
            t = __floats2bfloat162_rn(s[2 * kq + 1][2], s[2 * kq + 1][3]); pa[3] = *(uint32_t*)&t;
#pragma unroll
            for (int nd16 = 0; nd16 < 4; nd16++) {
                uint32_t vb[4];
                uint32_t off = (uint32_t)((kq * 16 + (sub & 1) * 8 + r8) * FTSTR
                                          + nd16 * 16 + (sub >> 1) * 8) * 2;
                LDMX4T(vb, aVt + off);
                MMA16816(o[nd16 * 2],     pa, vb[0], vb[1]);
                MMA16816(o[nd16 * 2 + 1], pa, vb[2], vb[3]);
            }
        }
        __syncthreads();   // protect smem before next tile load
    }

    // ---- write O ----
    const float inv0 = 1.0f / l0, inv1 = 1.0f / l1;
    const int row0 = q0 + wm + er, row1 = row0 + 8;
#pragma unroll
    for (int nd = 0; nd < 8; nd++) {
        const int col = hoff + nd * 8 + ec;
        *(float2*)(O + (size_t)row0 * EMB + col) = make_float2(o[nd][0] * inv0, o[nd][1] * inv0);
        *(float2*)(O + (size_t)row1 * EMB + col) = make_float2(o[nd][2] * inv1, o[nd][3] * inv1);
    }
}

// -------------------- fp32 SGEMM (embed only: trunc is discontinuous) ------
__global__ __launch_bounds__(256, 1) void sgemm_embed(
    const float* __restrict__ A, const float* __restrict__ B, float* __restrict__ C,
    int M, int N, int K, const float* __restrict__ bias, const float* __restrict__ extra)
{
    __shared__ float As[8][128];
    __shared__ float Bs[8][128];
    const int tid = threadIdx.x;
    const int bm = blockIdx.y * 128;
    const int bn = blockIdx.x * 128;
    const int lr = tid & 127;
    const int lc = (tid >> 7) << 2;
    const float* Ap = A + (size_t)(bm + lr) * K + lc;
    const float* Bp = B + (size_t)(bn + lr) * K + lc;
    const int tx = tid & 15, ty = tid >> 4;

    float acc[8][8];
#pragma unroll
    for (int i = 0; i < 8; i++)
#pragma unroll
        for (int j = 0; j < 8; j++) acc[i][j] = 0.f;

    for (int k0 = 0; k0 < K; k0 += 8) {
        float4 a4 = *(const float4*)(Ap + k0);
        float4 b4 = *(const float4*)(Bp + k0);
        As[lc + 0][lr] = a4.x; As[lc + 1][lr] = a4.y;
        As[lc + 2][lr] = a4.z; As[lc + 3][lr] = a4.w;
        Bs[lc + 0][lr] = b4.x; Bs[lc + 1][lr] = b4.y;
        Bs[lc + 2][lr] = b4.z; Bs[lc + 3][lr] = b4.w;
        __syncthreads();
#pragma unroll
        for (int k = 0; k < 8; k++) {
            float ra[8], rb[8];
            *(float4*)(ra)     = *(const float4*)&As[k][ty * 8];
            *(float4*)(ra + 4) = *(const float4*)&As[k][ty * 8 + 4];
            *(float4*)(rb)     = *(const float4*)&Bs[k][tx * 8];
            *(float4*)(rb + 4) = *(const float4*)&Bs[k][tx * 8 + 4];
#pragma unroll
            for (int i = 0; i < 8; i++)
#pragma unroll
                for (int j = 0; j < 8; j++)
                    acc[i][j] = fmaf(ra[i], rb[j], acc[i][j]);
        }
        __syncthreads();
    }

#pragma unroll
    for (int i = 0; i < 8; i++) {
        const int r = bm + ty * 8 + i;
#pragma unroll
        for (int j = 0; j < 8; j++) {
            const int c = bn + tx * 8 + j;
            C[(size_t)r * N + c] = truncf(acc[i][j] + bias[c]) + extra[(size_t)r * N + c];
        }
    }
}

// -------------------- layernorm over last dim (768) ------------------------
__global__ __launch_bounds__(256, 1) void ln_kernel(
    const float* __restrict__ in, float* __restrict__ out,
    const float* __restrict__ g, const float* __restrict__ b)
{
    __shared__ float rs[8], rs2[8];
    __shared__ float s_mu, s_rstd;
    const int r = blockIdx.x;
    const int tid = threadIdx.x;
    const float* row = in + (size_t)r * EMB;
    float v0 = row[tid], v1 = row[tid + 256], v2 = row[tid + 512];
    float s = v0 + v1 + v2;
    float s2 = v0 * v0 + v1 * v1 + v2 * v2;
#pragma unroll
    for (int m = 16; m; m >>= 1) {
        s += __shfl_xor_sync(0xffffffffu, s, m);
        s2 += __shfl_xor_sync(0xffffffffu, s2, m);
    }
    if ((tid & 31) == 0) { rs[tid >> 5] = s; rs2[tid >> 5] = s2; }
    __syncthreads();
    if (tid == 0) {
        float S = 0.f, S2 = 0.f;
#pragma unroll
        for (int i = 0; i < 8; i++) { S += rs[i]; S2 += rs2[i]; }
        float mu = S * (1.0f / EMB);
        float var = S2 * (1.0f / EMB) - mu * mu;
        s_mu = mu;
        s_rstd = rsqrtf(var + 1e-5f);
    }
    __syncthreads();
    float mu = s_mu, rstd = s_rstd;
    float* orow = out + (size_t)r * EMB;
    orow[tid]       = (v0 - mu) * rstd * g[tid]       + b[tid];
    orow[tid + 256] = (v1 - mu) * rstd * g[tid + 256] + b[tid + 256];
    orow[tid + 512] = (v2 - mu) * rstd * g[tid + 512] + b[tid + 512];
}

// -------------------- mean over sequence -----------------------------------
__global__ void mean_kernel(const float* __restrict__ in, float* __restrict__ out)
{
    int e = blockIdx.x * 256 + threadIdx.x;
    float s = 0.f;
    for (int n = 0; n < NSEQ; n++) s += in[(size_t)n * EMB + e];
    out[e] = s * (1.0f / NSEQ);
}

// -------------------- launch ------------------------------------------------
extern "C" void kernel_launch(void* const* d_in, const int* in_sizes, int n_in,
                              void* d_out, int out_size)
{
    (void)in_sizes; (void)n_in; (void)out_size;
    const float* x      = (const float*)d_in[0];
    const float* W_word = (const float*)d_in[2];
    const float* b_word = (const float*)d_in[3];
    const float* pos    = (const float*)d_in[4];
    const float* Wq     = (const float*)d_in[5];
    const float* Wk     = (const float*)d_in[6];
    const float* Wv     = (const float*)d_in[7];
    const float* Wo     = (const float*)d_in[8];
    const float* W1     = (const float*)d_in[9];
    const float* b1     = (const float*)d_in[10];
    const float* W2     = (const float*)d_in[11];
    const float* b2     = (const float*)d_in[12];
    const float* g1     = (const float*)d_in[13];
    const float* be1    = (const float*)d_in[14];
    const float* g2     = (const float*)d_in[15];
    const float* be2    = (const float*)d_in[16];
    float* out = (float*)d_out;

    float *p_out, *p_q, *p_k, *p_v, *p_att, *p_tmp, *p_xm, *p_ff;
    cudaGetSymbolAddress((void**)&p_out, g_out);
    cudaGetSymbolAddress((void**)&p_q,   g_q);
    cudaGetSymbolAddress((void**)&p_k,   g_k);
    cudaGetSymbolAddress((void**)&p_v,   g_v);
    cudaGetSymbolAddress((void**)&p_att, g_att);
    cudaGetSymbolAddress((void**)&p_tmp, g_tmp);
    cudaGetSymbolAddress((void**)&p_xm,  g_xm);
    cudaGetSymbolAddress((void**)&p_ff,  g_ff);

    cudaFuncSetAttribute(mma_gemm<MODE_RES>,   cudaFuncAttributeMaxDynamicSharedMemorySize, GEMM_DSMEM);
    cudaFuncSetAttribute(mma_gemm<MODE_BRELU>, cudaFuncAttributeMaxDynamicSharedMemorySize, GEMM_DSMEM);
    cudaFuncSetAttribute(mma_gemm<MODE_BRES>,  cudaFuncAttributeMaxDynamicSharedMemorySize, GEMM_DSMEM);
    cudaFuncSetAttribute(mma_qkv,              cudaFuncAttributeMaxDynamicSharedMemorySize, GEMM_DSMEM);
    cudaFuncSetAttribute(flash_hmma,           cudaFuncAttributeMaxDynamicSharedMemorySize, FLASH_DSMEM);

    dim3 blk(256);
    dim3 gEE(EMB / 128, NSEQ / 128);       // 6 x 24
    dim3 gQKV(EMB / 128, NSEQ / 128, 3);   // 6 x 24 x 3
    dim3 gFF(FFDIM / 128, NSEQ / 128);     // 24 x 24
    dim3 gFL(NSEQ / 128, NHEAD);           // 24 x 12

    // embed: out = trunc(x @ Ww^T + b_word) + pos   (fp32: trunc discontinuity)
    sgemm_embed<<<gEE, blk>>>(x, W_word, p_out, NSEQ, EMB, EMB, b_word, pos);

    for (int l = 0; l < NLAYER; l++) {
        const float* wq = Wq + (size_t)l * EMB * EMB;
        const float* wk = Wk + (size_t)l * EMB * EMB;
        const float* wv = Wv + (size_t)l * EMB * EMB;
        const float* wo = Wo + (size_t)l * EMB * EMB;
        const float* w1 = W1 + (size_t)l * FFDIM * EMB;
        const float* w2 = W2 + (size_t)l * EMB * FFDIM;

        mma_qkv<<<gQKV, blk, GEMM_DSMEM>>>(p_out, wq, wk, wv, p_q, p_k, p_v);

        flash_hmma<<<gFL, blk, FLASH_DSMEM>>>(p_q, p_k, p_v, p_att);

        mma_gemm<MODE_RES><<<gEE, blk, GEMM_DSMEM>>>(p_att, wo, p_tmp, EMB, EMB, nullptr, p_out);
        ln_kernel<<<NSEQ, 256>>>(p_tmp, p_xm, g1 + (size_t)l * EMB, be1 + (size_t)l * EMB);

        mma_gemm<MODE_BRELU><<<gFF, blk, GEMM_DSMEM>>>(p_xm, w1, p_ff, FFDIM, EMB,
                                                       b1 + (size_t)l * FFDIM, nullptr);
        mma_gemm<MODE_BRES><<<gEE, blk, GEMM_DSMEM>>>(p_ff, w2, p_tmp, EMB, FFDIM,
                                                      b2 + (size_t)l * EMB, p_xm);
        ln_kernel<<<NSEQ, 256>>>(p_tmp, p_out, g2 + (size_t)l * EMB, be2 + (size_t)l * EMB);
    }

    mean_kernel<<<3, 256>>>(p_out, out);
}